// round 2
// baseline (speedup 1.0000x reference)
#include <cuda_runtime.h>
#include <cstdint>
#include <cstddef>

// Problem dims
#define Bq   4
#define Lq   1024
#define Mq   (Bq*Lq)     // 4096 tokens
#define Dq   1536        // hidden / K

// GEMM tiling
#define BM 128
#define BN 128
#define BK 16

// Scratch (no cudaMalloc allowed): h buffer + decoded mask
__device__ float g_h[(size_t)Mq * Dq];
__device__ float g_mask[Mq];

// ---------------- packed f32x2 helpers (sm_100+) ----------------
__device__ __forceinline__ unsigned long long pk2(float lo, float hi) {
    unsigned long long r;
    asm("mov.b64 %0,{%1,%2};" : "=l"(r) : "f"(lo), "f"(hi));
    return r;
}
__device__ __forceinline__ unsigned long long f2fma(unsigned long long a,
                                                    unsigned long long b,
                                                    unsigned long long c) {
    unsigned long long d;
    asm("fma.rn.f32x2 %0,%1,%2,%3;" : "=l"(d) : "l"(a), "l"(b), "l"(c));
    return d;
}
__device__ __forceinline__ void upk2(unsigned long long p, float& lo, float& hi) {
    asm("mov.b64 {%0,%1},%2;" : "=f"(lo), "=f"(hi) : "l"(p));
}

// ---------------- mask decode: bool(u8) / int32 / float32 agnostic ----------------
__global__ void decode_mask_kernel(const void* __restrict__ mraw) {
    __shared__ int flg[2];
    const unsigned char* b = (const unsigned char*)mraw;
    const int t = threadIdx.x;
    if (t < 2) flg[t] = 0;
    __syncthreads();
    int f_wide = 0, f_byte = 0;
    for (int i = t; i < Mq; i += blockDim.x) {
        unsigned char v = b[i];          // first Mq bytes exist in every encoding
        if (v > 1) f_wide = 1;           // only float32 encoding has bytes >1
        if (v && (i & 3)) f_byte = 1;    // u8 bools have ones off 4-byte grid
    }
    if (f_wide) atomicOr(&flg[0], 1);
    if (f_byte) atomicOr(&flg[1], 1);
    __syncthreads();
    const int wide = flg[0], byt = flg[1];
    for (int i = t; i < Mq; i += blockDim.x) {
        float m;
        if (wide)      m = (((const float*)mraw)[i] != 0.f) ? 1.f : 0.f;
        else if (byt)  m = b[i] ? 1.f : 0.f;
        else           m = (((const int*)mraw)[i] != 0) ? 1.f : 0.f;
        g_mask[i] = m;
    }
}

// ---------------- GEMM1 + bias + exact GELU ----------------
// h[m,e] = gelu( sum_d x[m,d] * w1[e,d] + b1[e] )
__global__ __launch_bounds__(256, 2) void gemm_gelu_kernel(
    const float* __restrict__ X,     // [Mq, Dq]
    const float* __restrict__ W,     // [Dq(E), Dq(D)]
    const float* __restrict__ bias)  // [Dq]
{
    __shared__ float As[BK][BM];
    __shared__ float Bs[BK][BN];
    const int m0 = blockIdx.y * BM;
    const int n0 = blockIdx.x * BN;
    const int tid = threadIdx.x;
    const int tx = tid & 15;    // 16 x 16 thread grid, 8x8 per thread
    const int ty = tid >> 4;

    unsigned long long c2[8][4];
#pragma unroll
    for (int i = 0; i < 8; i++)
#pragma unroll
        for (int j = 0; j < 4; j++) c2[i][j] = 0ull;   // {0.f, 0.f}

    // Global->smem mapping: 512 float4 per tile, 2 per thread
    const int lr = tid >> 2;            // 0..63
    const int lc = (tid & 3) * 4;       // 0,4,8,12
    const float* xp = X + (size_t)(m0 + lr) * Dq + lc;
    const float* wp = W + (size_t)(n0 + lr) * Dq + lc;

    for (int k0 = 0; k0 < Dq; k0 += BK) {
        float4 a0 = *(const float4*)(xp + k0);
        float4 a1 = *(const float4*)(xp + (size_t)64 * Dq + k0);
        float4 w0 = *(const float4*)(wp + k0);
        float4 w1v = *(const float4*)(wp + (size_t)64 * Dq + k0);
        __syncthreads();   // previous-iter consumers done before overwrite
        As[lc + 0][lr] = a0.x; As[lc + 1][lr] = a0.y; As[lc + 2][lr] = a0.z; As[lc + 3][lr] = a0.w;
        As[lc + 0][lr + 64] = a1.x; As[lc + 1][lr + 64] = a1.y; As[lc + 2][lr + 64] = a1.z; As[lc + 3][lr + 64] = a1.w;
        Bs[lc + 0][lr] = w0.x; Bs[lc + 1][lr] = w0.y; Bs[lc + 2][lr] = w0.z; Bs[lc + 3][lr] = w0.w;
        Bs[lc + 0][lr + 64] = w1v.x; Bs[lc + 1][lr + 64] = w1v.y; Bs[lc + 2][lr + 64] = w1v.z; Bs[lc + 3][lr + 64] = w1v.w;
        __syncthreads();
#pragma unroll
        for (int kk = 0; kk < BK; kk++) {
            float4 af0 = *(const float4*)&As[kk][ty * 8];
            float4 af1 = *(const float4*)&As[kk][ty * 8 + 4];
            float4 bf0 = *(const float4*)&Bs[kk][tx * 8];
            float4 bf1 = *(const float4*)&Bs[kk][tx * 8 + 4];
            unsigned long long bp[4];
            bp[0] = pk2(bf0.x, bf0.y); bp[1] = pk2(bf0.z, bf0.w);
            bp[2] = pk2(bf1.x, bf1.y); bp[3] = pk2(bf1.z, bf1.w);
            float aa[8] = {af0.x, af0.y, af0.z, af0.w, af1.x, af1.y, af1.z, af1.w};
#pragma unroll
            for (int i = 0; i < 8; i++) {
                unsigned long long ap = pk2(aa[i], aa[i]);
#pragma unroll
                for (int j = 0; j < 4; j++) c2[i][j] = f2fma(ap, bp[j], c2[i][j]);
            }
        }
    }

    // Epilogue: + bias, exact GELU (x * Phi(x)), store h
#pragma unroll
    for (int i = 0; i < 8; i++) {
        const int row = m0 + ty * 8 + i;
        float* hp = g_h + (size_t)row * Dq + n0 + tx * 8;
#pragma unroll
        for (int j = 0; j < 4; j++) {
            float lo, hi;
            upk2(c2[i][j], lo, hi);
            const int col = n0 + tx * 8 + j * 2;
            float v0 = lo + bias[col];
            float v1 = hi + bias[col + 1];
            v0 = v0 * normcdff(v0);
            v1 = v1 * normcdff(v1);
            hp[j * 2] = v0;
            hp[j * 2 + 1] = v1;
        }
    }
}

// ---------------- LN + 9-way head GEMM + geometry epilogue ----------------
__global__ __launch_bounds__(128) void head_kernel(
    const float* __restrict__ ln_g, const float* __restrict__ ln_b,
    const float* __restrict__ w2,   const float* __restrict__ b2,
    const float* __restrict__ affine, float* __restrict__ out)
{
    const int row = blockIdx.x;
    const int t = threadIdx.x;        // 128 threads
    const int warp = t >> 5, lane = t & 31;
    __shared__ float rstat[2][4];
    __shared__ float red[9][4];

    const float* hrow = g_h + (size_t)row * Dq;
    float v[12];
    float s = 0.f, s2 = 0.f;
#pragma unroll
    for (int i = 0; i < 12; i++) {
        float x = hrow[t + i * 128];
        v[i] = x; s += x; s2 += x * x;
    }
#pragma unroll
    for (int off = 16; off > 0; off >>= 1) {
        s  += __shfl_down_sync(0xffffffffu, s,  off);
        s2 += __shfl_down_sync(0xffffffffu, s2, off);
    }
    if (lane == 0) { rstat[0][warp] = s; rstat[1][warp] = s2; }
    __syncthreads();
    const float S  = rstat[0][0] + rstat[0][1] + rstat[0][2] + rstat[0][3];
    const float Q  = rstat[1][0] + rstat[1][1] + rstat[1][2] + rstat[1][3];
    const float mu = S * (1.f / Dq);
    const float var = Q * (1.f / Dq) - mu * mu;
    const float rs = rsqrtf(var + 1e-5f);

    float acc[9];
#pragma unroll
    for (int o = 0; o < 9; o++) acc[o] = 0.f;
#pragma unroll
    for (int i = 0; i < 12; i++) {
        const int d = t + i * 128;
        const float hv = (v[i] - mu) * rs * ln_g[d] + ln_b[d];
#pragma unroll
        for (int o = 0; o < 9; o++) acc[o] += hv * w2[o * Dq + d];
    }
#pragma unroll
    for (int o = 0; o < 9; o++)
#pragma unroll
        for (int off = 16; off > 0; off >>= 1)
            acc[o] += __shfl_down_sync(0xffffffffu, acc[o], off);
    if (lane == 0) {
#pragma unroll
        for (int o = 0; o < 9; o++) red[o][warp] = acc[o];
    }
    __syncthreads();

    if (t == 0) {
        float p[9];
#pragma unroll
        for (int o = 0; o < 9; o++)
            p[o] = red[o][0] + red[o][1] + red[o][2] + red[o][3] + b2[o];

        float tr0 = p[0] * 10.f, tr1 = p[1] * 10.f, tr2 = p[2] * 10.f;
        float xv0 = p[3], xv1 = p[4], xv2 = p[5];
        float yv0 = p[6], yv1 = p[7], yv2 = p[8];
        float inx = 1.f / (sqrtf(xv0 * xv0 + xv1 * xv1 + xv2 * xv2) + 1e-5f);
        xv0 *= inx; xv1 *= inx; xv2 *= inx;
        float iny = 1.f / (sqrtf(yv0 * yv0 + yv1 * yv1 + yv2 * yv2) + 1e-5f);
        yv0 *= iny; yv1 *= iny; yv2 *= iny;

        // Gram-Schmidt on (trans - neg_x, p_xy - trans) == (-xv, yv)
        float a0 = -xv0, a1 = -xv1, a2 = -xv2;
        float an = rsqrtf(a0 * a0 + a1 * a1 + a2 * a2 + 1e-12f);
        float e0x = a0 * an, e0y = a1 * an, e0z = a2 * an;
        float dd = e0x * yv0 + e0y * yv1 + e0z * yv2;
        float e1x = yv0 - e0x * dd, e1y = yv1 - e0y * dd, e1z = yv2 - e0z * dd;
        float en = rsqrtf(e1x * e1x + e1y * e1y + e1z * e1z + 1e-12f);
        e1x *= en; e1y *= en; e1z *= en;
        float e2x = e0y * e1z - e0z * e1y;
        float e2y = e0z * e1x - e0x * e1z;
        float e2z = e0x * e1y - e0y * e1x;

        // Ru columns = e0,e1,e2  (stack axis=-1)
        float Ru[3][3] = {{e0x, e1x, e2x}, {e0y, e1y, e2y}, {e0z, e1z, e2z}};
        float tu0 = tr0, tu1 = tr1, tu2 = tr2;
        if (g_mask[row] == 0.f) {
            Ru[0][0] = 1.f; Ru[0][1] = 0.f; Ru[0][2] = 0.f;
            Ru[1][0] = 0.f; Ru[1][1] = 1.f; Ru[1][2] = 0.f;
            Ru[2][0] = 0.f; Ru[2][1] = 0.f; Ru[2][2] = 1.f;
            tu0 = 0.f; tu1 = 0.f; tu2 = 0.f;
        }

        const float* af = affine + (size_t)row * 12;
        float R0m[3][3] = {{af[0], af[1], af[2]}, {af[3], af[4], af[5]}, {af[6], af[7], af[8]}};
        float t0x = af[9], t0y = af[10], t0z = af[11];

        float R[3][3], tt[3];
#pragma unroll
        for (int i = 0; i < 3; i++) {
#pragma unroll
            for (int j = 0; j < 3; j++)
                R[i][j] = R0m[i][0] * Ru[0][j] + R0m[i][1] * Ru[1][j] + R0m[i][2] * Ru[2][j];
        }
        tt[0] = R0m[0][0] * tu0 + R0m[0][1] * tu1 + R0m[0][2] * tu2 + t0x;
        tt[1] = R0m[1][0] * tu0 + R0m[1][1] * tu1 + R0m[1][2] * tu2 + t0y;
        tt[2] = R0m[2][0] * tu0 + R0m[2][1] * tu1 + R0m[2][2] * tu2 + t0z;

        float* oa = out + (size_t)row * 12;
        oa[0] = R[0][0]; oa[1] = R[0][1]; oa[2] = R[0][2];
        oa[3] = R[1][0]; oa[4] = R[1][1]; oa[5] = R[1][2];
        oa[6] = R[2][0]; oa[7] = R[2][1]; oa[8] = R[2][2];
        oa[9] = tt[0]; oa[10] = tt[1]; oa[11] = tt[2];

        const float BBc[3][3] = {{-0.525f, 1.363f, 0.f}, {0.f, 0.f, 0.f}, {1.526f, 0.f, 0.f}};
        float* ox = out + (size_t)Mq * 12 + (size_t)row * 9;
#pragma unroll
        for (int a = 0; a < 3; a++) {
#pragma unroll
            for (int i = 0; i < 3; i++)
                ox[a * 3 + i] = R[i][0] * BBc[a][0] + R[i][1] * BBc[a][1] + R[i][2] * BBc[a][2] + tt[i];
        }
    }
}

// ---------------- launcher ----------------
extern "C" void kernel_launch(void* const* d_in, const int* in_sizes, int n_in,
                              void* d_out, int out_size) {
    const float* x      = (const float*)d_in[0];
    const float* affine = (const float*)d_in[1];
    const void*  mraw   = d_in[2];
    const float* w1     = (const float*)d_in[3];
    const float* b1     = (const float*)d_in[4];
    const float* ln_g   = (const float*)d_in[5];
    const float* ln_b   = (const float*)d_in[6];
    const float* w2     = (const float*)d_in[7];
    const float* b2     = (const float*)d_in[8];
    float* out = (float*)d_out;
    (void)in_sizes; (void)n_in; (void)out_size;

    decode_mask_kernel<<<1, 256>>>(mraw);
    dim3 grid(Dq / BN, Mq / BM);   // (12, 32)
    gemm_gelu_kernel<<<grid, 256>>>(x, w1, b1);
    head_kernel<<<Mq, 128>>>(ln_g, ln_b, w2, b2, affine, out);
}

// round 5
// speedup vs baseline: 2.2256x; 2.2256x over previous
#include <cuda_runtime.h>
#include <cuda_bf16.h>
#include <cstdint>
#include <cstddef>

// Problem dims
#define Bq   4
#define Lq   1024
#define Mq   (Bq*Lq)     // 4096 tokens
#define Dq   1536        // hidden / K
#define NC   (Dq/32)     // 48 k-chunks of 32

// Scratch (no cudaMalloc allowed)
__device__ __align__(16) __nv_bfloat16 g_ah[(size_t)Mq * Dq];
__device__ __align__(16) __nv_bfloat16 g_al[(size_t)Mq * Dq];
__device__ __align__(16) __nv_bfloat16 g_bh[(size_t)Dq * Dq];
__device__ __align__(16) __nv_bfloat16 g_bl[(size_t)Dq * Dq];
__device__ __align__(16) float g_h[(size_t)Mq * Dq];
__device__ float g_mask[Mq];

// ---------- PTX helpers (baseline ISA only: sm_80-class, assembles on sm_103) ----------
__device__ __forceinline__ uint32_t smem_u32(const void* p) {
    uint32_t a;
    asm("{ .reg .u64 t; cvta.to.shared.u64 t, %1; cvt.u32.u64 %0, t; }" : "=r"(a) : "l"(p));
    return a;
}
__device__ __forceinline__ void cp16(uint32_t dst, const void* src) {
    asm volatile("cp.async.cg.shared.global [%0], [%1], 16;" :: "r"(dst), "l"(src) : "memory");
}
__device__ __forceinline__ void cp_commit() {
    asm volatile("cp.async.commit_group;" ::: "memory");
}
template <int N> __device__ __forceinline__ void cp_wait() {
    asm volatile("cp.async.wait_group %0;" :: "n"(N) : "memory");
}
__device__ __forceinline__ void ldmx4(uint32_t* r, uint32_t addr) {
    asm volatile("ldmatrix.sync.aligned.m8n8.x4.shared.b16 {%0,%1,%2,%3}, [%4];"
                 : "=r"(r[0]), "=r"(r[1]), "=r"(r[2]), "=r"(r[3]) : "r"(addr));
}
__device__ __forceinline__ void mma16816(float* c, const uint32_t* a, const uint32_t* b) {
    asm volatile(
        "mma.sync.aligned.m16n8k16.row.col.f32.bf16.bf16.f32 "
        "{%0,%1,%2,%3}, {%4,%5,%6,%7}, {%8,%9}, {%0,%1,%2,%3};"
        : "+f"(c[0]), "+f"(c[1]), "+f"(c[2]), "+f"(c[3])
        : "r"(a[0]), "r"(a[1]), "r"(a[2]), "r"(a[3]), "r"(b[0]), "r"(b[1]));
}

// SMEM layout: 4 padded tiles per stage, rows of 32 bf16 padded to 40 (80 B stride)
#define ROWB  80u
#define TILE  10240u       // 128 * 80
#define AHOF  0u
#define ALOF  10240u
#define BHOF  20480u
#define BLOF  30720u
#define STG   40960u
#define SMEM_TOTAL (2u * STG)   // 81920 B (dynamic)

// ================= prep: fp32 -> bf16 hi/lo split + mask decode =================
#define XBLK (Mq * (Dq/4) / 256)   // 6144
#define WBLK (Dq * (Dq/4) / 256)   // 2304

__global__ __launch_bounds__(256) void prep_kernel(
    const float* __restrict__ x, const float* __restrict__ w, const void* __restrict__ mraw)
{
    const int b = blockIdx.x;
    const int t = threadIdx.x;
    if (b < XBLK + WBLK) {
        const bool isx = b < XBLK;
        const size_t i = (size_t)(isx ? b : b - XBLK) * 256 + t;
        const float4 v = isx ? ((const float4*)x)[i] : ((const float4*)w)[i];
        __nv_bfloat16 h0 = __float2bfloat16_rn(v.x);
        __nv_bfloat16 h1 = __float2bfloat16_rn(v.y);
        __nv_bfloat16 h2 = __float2bfloat16_rn(v.z);
        __nv_bfloat16 h3 = __float2bfloat16_rn(v.w);
        __nv_bfloat16 l0 = __float2bfloat16_rn(v.x - __bfloat162float(h0));
        __nv_bfloat16 l1 = __float2bfloat16_rn(v.y - __bfloat162float(h1));
        __nv_bfloat16 l2 = __float2bfloat16_rn(v.z - __bfloat162float(h2));
        __nv_bfloat16 l3 = __float2bfloat16_rn(v.w - __bfloat162float(h3));
        ushort4 ph, pl;
        ph.x = __bfloat16_as_ushort(h0); ph.y = __bfloat16_as_ushort(h1);
        ph.z = __bfloat16_as_ushort(h2); ph.w = __bfloat16_as_ushort(h3);
        pl.x = __bfloat16_as_ushort(l0); pl.y = __bfloat16_as_ushort(l1);
        pl.z = __bfloat16_as_ushort(l2); pl.w = __bfloat16_as_ushort(l3);
        if (isx) { ((ushort4*)g_ah)[i] = ph; ((ushort4*)g_al)[i] = pl; }
        else     { ((ushort4*)g_bh)[i] = ph; ((ushort4*)g_bl)[i] = pl; }
    } else {
        __shared__ int flg[2];
        const unsigned char* bb = (const unsigned char*)mraw;
        if (t < 2) flg[t] = 0;
        __syncthreads();
        int f_wide = 0, f_byte = 0;
        for (int i = t; i < Mq; i += 256) {
            unsigned char v = bb[i];
            if (v > 1) f_wide = 1;
            if (v && (i & 3)) f_byte = 1;
        }
        if (f_wide) atomicOr(&flg[0], 1);
        if (f_byte) atomicOr(&flg[1], 1);
        __syncthreads();
        const int wide = flg[0], byt = flg[1];
        for (int i = t; i < Mq; i += 256) {
            float m;
            if (wide)      m = (((const float*)mraw)[i] != 0.f) ? 1.f : 0.f;
            else if (byt)  m = bb[i] ? 1.f : 0.f;
            else           m = (((const int*)mraw)[i] != 0) ? 1.f : 0.f;
            g_mask[i] = m;
        }
    }
}

// ================= GEMM1 (HMMA bf16 3-term split) + bias + exact GELU =================
__global__ __launch_bounds__(256, 2) void gemm_mma_kernel(const float* __restrict__ bias)
{
    extern __shared__ char smem[];
    const uint32_t sbase = smem_u32(smem);
    const int tid  = threadIdx.x;
    const int wid  = tid >> 5, lane = tid & 31;
    const int m0 = blockIdx.y * 128;
    const int n0 = blockIdx.x * 128;
    const int wr = wid & 1;          // 2 row groups of 64
    const int wc = wid >> 1;         // 4 col groups of 32

    float acc[4][4][4];
#pragma unroll
    for (int i = 0; i < 4; i++)
#pragma unroll
        for (int j = 0; j < 4; j++)
#pragma unroll
            for (int q = 0; q < 4; q++) acc[i][j][q] = 0.f;

    // loader mapping: unit u in [0,512) per tile: row=u>>2, quad=u&3; thread handles u=t, t+256
    const int r0 = tid >> 2;
    const int q8 = (tid & 3) * 8;                 // element offset in row
    const uint32_t so0 = (uint32_t)r0 * ROWB + (uint32_t)(tid & 3) * 16;
    const uint32_t so1 = so0 + 64u * ROWB;
    const __nv_bfloat16* pah0 = g_ah + (size_t)(m0 + r0) * Dq + q8;
    const __nv_bfloat16* pah1 = pah0 + (size_t)64 * Dq;
    const __nv_bfloat16* pal0 = g_al + (size_t)(m0 + r0) * Dq + q8;
    const __nv_bfloat16* pal1 = pal0 + (size_t)64 * Dq;
    const __nv_bfloat16* pbh0 = g_bh + (size_t)(n0 + r0) * Dq + q8;
    const __nv_bfloat16* pbh1 = pbh0 + (size_t)64 * Dq;
    const __nv_bfloat16* pbl0 = g_bl + (size_t)(n0 + r0) * Dq + q8;
    const __nv_bfloat16* pbl1 = pbl0 + (size_t)64 * Dq;

#define ISSUE(c, s)                                                   \
    do {                                                              \
        const int k0 = (c) * 32;                                      \
        const uint32_t d = sbase + (uint32_t)(s) * STG;               \
        cp16(d + AHOF + so0, pah0 + k0);                              \
        cp16(d + AHOF + so1, pah1 + k0);                              \
        cp16(d + ALOF + so0, pal0 + k0);                              \
        cp16(d + ALOF + so1, pal1 + k0);                              \
        cp16(d + BHOF + so0, pbh0 + k0);                              \
        cp16(d + BHOF + so1, pbh1 + k0);                              \
        cp16(d + BLOF + so0, pbl0 + k0);                              \
        cp16(d + BLOF + so1, pbl1 + k0);                              \
        cp_commit();                                                  \
    } while (0)

    // ldmatrix address components (per lane)
    const uint32_t a_row = (uint32_t)(wr * 64 + (lane & 15)) * ROWB;
    const uint32_t a_k   = (uint32_t)((lane >> 4) << 3) * 2;
    const uint32_t b_row = (uint32_t)(wc * 32 + ((lane >> 4) << 3) + (lane & 7)) * ROWB;
    const uint32_t b_k   = (uint32_t)(((lane >> 3) & 1) << 3) * 2;

    ISSUE(0, 0);
    for (int c = 0; c < NC; ++c) {
        const int s = c & 1;
        if (c + 1 < NC) { ISSUE(c + 1, s ^ 1); cp_wait<1>(); }
        else            { cp_wait<0>(); }
        __syncthreads();

        const uint32_t base = sbase + (uint32_t)s * STG;
#pragma unroll
        for (int k16 = 0; k16 < 2; ++k16) {
            const uint32_t koff = (uint32_t)k16 * 32;   // 16 bf16 = 32 B
            uint32_t ah[4][4], bh[8], bl[8];
#pragma unroll
            for (int i = 0; i < 4; ++i)
                ldmx4(ah[i], base + AHOF + a_row + (uint32_t)(i * 16) * ROWB + a_k + koff);
#pragma unroll
            for (int j2 = 0; j2 < 2; ++j2) {
                ldmx4(&bh[j2 * 4], base + BHOF + b_row + (uint32_t)(j2 * 16) * ROWB + b_k + koff);
                ldmx4(&bl[j2 * 4], base + BLOF + b_row + (uint32_t)(j2 * 16) * ROWB + b_k + koff);
            }
#pragma unroll
            for (int i = 0; i < 4; ++i)
#pragma unroll
                for (int j = 0; j < 4; ++j) mma16816(acc[i][j], ah[i], &bh[j * 2]);
#pragma unroll
            for (int i = 0; i < 4; ++i)
#pragma unroll
                for (int j = 0; j < 4; ++j) mma16816(acc[i][j], ah[i], &bl[j * 2]);
            uint32_t al[4][4];
#pragma unroll
            for (int i = 0; i < 4; ++i)
                ldmx4(al[i], base + ALOF + a_row + (uint32_t)(i * 16) * ROWB + a_k + koff);
#pragma unroll
            for (int i = 0; i < 4; ++i)
#pragma unroll
                for (int j = 0; j < 4; ++j) mma16816(acc[i][j], al[i], &bh[j * 2]);
        }
        __syncthreads();
    }

    // Epilogue: + bias, exact GELU, store h (fp32)
#pragma unroll
    for (int i = 0; i < 4; ++i) {
        const int row0 = m0 + wr * 64 + i * 16 + (lane >> 2);
#pragma unroll
        for (int j = 0; j < 4; ++j) {
            const int col = n0 + wc * 32 + j * 8 + (lane & 3) * 2;
            const float b0 = bias[col], b1 = bias[col + 1];
            float v0 = acc[i][j][0] + b0, v1 = acc[i][j][1] + b1;
            float v2 = acc[i][j][2] + b0, v3 = acc[i][j][3] + b1;
            float2 o01, o23;
            o01.x = v0 * normcdff(v0); o01.y = v1 * normcdff(v1);
            o23.x = v2 * normcdff(v2); o23.y = v3 * normcdff(v3);
            *(float2*)(g_h + (size_t)row0 * Dq + col)       = o01;
            *(float2*)(g_h + (size_t)(row0 + 8) * Dq + col) = o23;
        }
    }
}

// ================= LN + 9-way head GEMM + geometry epilogue =================
__global__ __launch_bounds__(128) void head_kernel(
    const float* __restrict__ ln_g, const float* __restrict__ ln_b,
    const float* __restrict__ w2,   const float* __restrict__ b2,
    const float* __restrict__ affine, float* __restrict__ out)
{
    const int row = blockIdx.x;
    const int t = threadIdx.x;
    const int warp = t >> 5, lane = t & 31;
    __shared__ float rstat[2][4];
    __shared__ float red[9][4];

    const float* hrow = g_h + (size_t)row * Dq;
    float v[12];
    float s = 0.f, s2 = 0.f;
#pragma unroll
    for (int i = 0; i < 12; i++) {
        float x = hrow[t + i * 128];
        v[i] = x; s += x; s2 += x * x;
    }
#pragma unroll
    for (int off = 16; off > 0; off >>= 1) {
        s  += __shfl_down_sync(0xffffffffu, s,  off);
        s2 += __shfl_down_sync(0xffffffffu, s2, off);
    }
    if (lane == 0) { rstat[0][warp] = s; rstat[1][warp] = s2; }
    __syncthreads();
    const float S  = rstat[0][0] + rstat[0][1] + rstat[0][2] + rstat[0][3];
    const float Q  = rstat[1][0] + rstat[1][1] + rstat[1][2] + rstat[1][3];
    const float mu = S * (1.f / Dq);
    const float var = Q * (1.f / Dq) - mu * mu;
    const float rs = rsqrtf(var + 1e-5f);

    float acc[9];
#pragma unroll
    for (int o = 0; o < 9; o++) acc[o] = 0.f;
#pragma unroll
    for (int i = 0; i < 12; i++) {
        const int d = t + i * 128;
        const float hv = (v[i] - mu) * rs * ln_g[d] + ln_b[d];
#pragma unroll
        for (int o = 0; o < 9; o++) acc[o] += hv * w2[o * Dq + d];
    }
#pragma unroll
    for (int o = 0; o < 9; o++)
#pragma unroll
        for (int off = 16; off > 0; off >>= 1)
            acc[o] += __shfl_down_sync(0xffffffffu, acc[o], off);
    if (lane == 0) {
#pragma unroll
        for (int o = 0; o < 9; o++) red[o][warp] = acc[o];
    }
    __syncthreads();

    if (t == 0) {
        float p[9];
#pragma unroll
        for (int o = 0; o < 9; o++)
            p[o] = red[o][0] + red[o][1] + red[o][2] + red[o][3] + b2[o];

        float tr0 = p[0] * 10.f, tr1 = p[1] * 10.f, tr2 = p[2] * 10.f;
        float xv0 = p[3], xv1 = p[4], xv2 = p[5];
        float yv0 = p[6], yv1 = p[7], yv2 = p[8];
        float inx = 1.f / (sqrtf(xv0 * xv0 + xv1 * xv1 + xv2 * xv2) + 1e-5f);
        xv0 *= inx; xv1 *= inx; xv2 *= inx;
        float iny = 1.f / (sqrtf(yv0 * yv0 + yv1 * yv1 + yv2 * yv2) + 1e-5f);
        yv0 *= iny; yv1 *= iny; yv2 *= iny;

        float a0 = -xv0, a1 = -xv1, a2 = -xv2;
        float an = rsqrtf(a0 * a0 + a1 * a1 + a2 * a2 + 1e-12f);
        float e0x = a0 * an, e0y = a1 * an, e0z = a2 * an;
        float dd = e0x * yv0 + e0y * yv1 + e0z * yv2;
        float e1x = yv0 - e0x * dd, e1y = yv1 - e0y * dd, e1z = yv2 - e0z * dd;
        float en = rsqrtf(e1x * e1x + e1y * e1y + e1z * e1z + 1e-12f);
        e1x *= en; e1y *= en; e1z *= en;
        float e2x = e0y * e1z - e0z * e1y;
        float e2y = e0z * e1x - e0x * e1z;
        float e2z = e0x * e1y - e0y * e1x;

        float Ru[3][3] = {{e0x, e1x, e2x}, {e0y, e1y, e2y}, {e0z, e1z, e2z}};
        float tu0 = tr0, tu1 = tr1, tu2 = tr2;
        if (g_mask[row] == 0.f) {
            Ru[0][0] = 1.f; Ru[0][1] = 0.f; Ru[0][2] = 0.f;
            Ru[1][0] = 0.f; Ru[1][1] = 1.f; Ru[1][2] = 0.f;
            Ru[2][0] = 0.f; Ru[2][1] = 0.f; Ru[2][2] = 1.f;
            tu0 = 0.f; tu1 = 0.f; tu2 = 0.f;
        }

        const float* af = affine + (size_t)row * 12;
        float R0m[3][3] = {{af[0], af[1], af[2]}, {af[3], af[4], af[5]}, {af[6], af[7], af[8]}};
        float t0x = af[9], t0y = af[10], t0z = af[11];

        float R[3][3], tt[3];
#pragma unroll
        for (int i = 0; i < 3; i++) {
#pragma unroll
            for (int j = 0; j < 3; j++)
                R[i][j] = R0m[i][0] * Ru[0][j] + R0m[i][1] * Ru[1][j] + R0m[i][2] * Ru[2][j];
        }
        tt[0] = R0m[0][0] * tu0 + R0m[0][1] * tu1 + R0m[0][2] * tu2 + t0x;
        tt[1] = R0m[1][0] * tu0 + R0m[1][1] * tu1 + R0m[1][2] * tu2 + t0y;
        tt[2] = R0m[2][0] * tu0 + R0m[2][1] * tu1 + R0m[2][2] * tu2 + t0z;

        float* oa = out + (size_t)row * 12;
        oa[0] = R[0][0]; oa[1] = R[0][1]; oa[2] = R[0][2];
        oa[3] = R[1][0]; oa[4] = R[1][1]; oa[5] = R[1][2];
        oa[6] = R[2][0]; oa[7] = R[2][1]; oa[8] = R[2][2];
        oa[9] = tt[0]; oa[10] = tt[1]; oa[11] = tt[2];

        const float BBc[3][3] = {{-0.525f, 1.363f, 0.f}, {0.f, 0.f, 0.f}, {1.526f, 0.f, 0.f}};
        float* ox = out + (size_t)Mq * 12 + (size_t)row * 9;
#pragma unroll
        for (int a = 0; a < 3; a++) {
#pragma unroll
            for (int i = 0; i < 3; i++)
                ox[a * 3 + i] = R[i][0] * BBc[a][0] + R[i][1] * BBc[a][1] + R[i][2] * BBc[a][2] + tt[i];
        }
    }
}

// ================= launcher =================
extern "C" void kernel_launch(void* const* d_in, const int* in_sizes, int n_in,
                              void* d_out, int out_size) {
    const float* x      = (const float*)d_in[0];
    const float* affine = (const float*)d_in[1];
    const void*  mraw   = d_in[2];
    const float* w1     = (const float*)d_in[3];
    const float* b1     = (const float*)d_in[4];
    const float* ln_g   = (const float*)d_in[5];
    const float* ln_b   = (const float*)d_in[6];
    const float* w2     = (const float*)d_in[7];
    const float* b2     = (const float*)d_in[8];
    float* out = (float*)d_out;
    (void)in_sizes; (void)n_in; (void)out_size;

    static int attr_set = 0;
    if (!attr_set) {
        cudaFuncSetAttribute(gemm_mma_kernel, cudaFuncAttributeMaxDynamicSharedMemorySize, SMEM_TOTAL);
        attr_set = 1;
    }

    prep_kernel<<<XBLK + WBLK + 1, 256>>>(x, w1, mraw);
    dim3 grid(Dq / 128, Mq / 128);   // (12, 32)
    gemm_mma_kernel<<<grid, 256, SMEM_TOTAL>>>(b1);
    head_kernel<<<Mq, 128>>>(ln_g, ln_b, w2, b2, affine, out);
}

// round 10
// speedup vs baseline: 4.0891x; 1.8373x over previous
#include <cuda_runtime.h>
#include <cuda_fp16.h>
#include <cstdint>
#include <cstddef>

// Problem dims
#define Bq   4
#define Lq   1024
#define Mq   (Bq*Lq)     // 4096 tokens
#define Dq   1536        // hidden / K
#define NC   (Dq/64)     // 24 k-chunks of 64

// Scratch (no cudaMalloc allowed)
__device__ __align__(16) __half g_xh[(size_t)Mq * Dq];
__device__ __align__(16) __half g_wh[(size_t)Dq * Dq];
__device__ __align__(16) float g_h[(size_t)Mq * Dq];
__device__ float g_mask[Mq];

// ---------- PTX helpers (sm_80-class baseline ISA; assembles on sm_103) ----------
__device__ __forceinline__ uint32_t smem_u32(const void* p) {
    uint32_t a;
    asm("{ .reg .u64 t; cvta.to.shared.u64 t, %1; cvt.u32.u64 %0, t; }" : "=r"(a) : "l"(p));
    return a;
}
__device__ __forceinline__ void cp16(uint32_t dst, const void* src) {
    asm volatile("cp.async.cg.shared.global [%0], [%1], 16;" :: "r"(dst), "l"(src) : "memory");
}
__device__ __forceinline__ void cp_commit() {
    asm volatile("cp.async.commit_group;" ::: "memory");
}
template <int N> __device__ __forceinline__ void cp_wait() {
    asm volatile("cp.async.wait_group %0;" :: "n"(N) : "memory");
}
__device__ __forceinline__ void ldmx4(uint32_t* r, uint32_t addr) {
    asm volatile("ldmatrix.sync.aligned.m8n8.x4.shared.b16 {%0,%1,%2,%3}, [%4];"
                 : "=r"(r[0]), "=r"(r[1]), "=r"(r[2]), "=r"(r[3]) : "r"(addr));
}
__device__ __forceinline__ void ldmx2(uint32_t* r, uint32_t addr) {
    asm volatile("ldmatrix.sync.aligned.m8n8.x2.shared.b16 {%0,%1}, [%2];"
                 : "=r"(r[0]), "=r"(r[1]) : "r"(addr));
}
__device__ __forceinline__ void mma16816(float* c, const uint32_t* a, const uint32_t* b) {
    asm volatile(
        "mma.sync.aligned.m16n8k16.row.col.f32.f16.f16.f32 "
        "{%0,%1,%2,%3}, {%4,%5,%6,%7}, {%8,%9}, {%0,%1,%2,%3};"
        : "+f"(c[0]), "+f"(c[1]), "+f"(c[2]), "+f"(c[3])
        : "r"(a[0]), "r"(a[1]), "r"(a[2]), "r"(a[3]), "r"(b[0]), "r"(b[1]));
}

// SMEM: rows of 64 fp16 (128B) padded to 144B -> ldmatrix conflict-free
#define ROWB  144u
#define AOF   0u
#define BOF   18432u           // 128 * 144
#define STG   32256u           // + 96 * 144
#define NSTG  3
#define SMEM_TOTAL (NSTG * STG)   // 96768 B

// ================= prep: fp32 -> fp16 + mask decode =================
#define XBLK2 (Mq * (Dq/4) / 256)   // 6144
#define WBLK2 (Dq * (Dq/4) / 256)   // 2304

__global__ __launch_bounds__(256) void prep_kernel(
    const float* __restrict__ x, const float* __restrict__ w, const void* __restrict__ mraw)
{
    const int b = blockIdx.x;
    const int t = threadIdx.x;
    if (b < XBLK2 + WBLK2) {
        const bool isx = b < XBLK2;
        const size_t i = (size_t)(isx ? b : b - XBLK2) * 256 + t;
        const float4 v = isx ? ((const float4*)x)[i] : ((const float4*)w)[i];
        ushort4 p;
        p.x = __half_as_ushort(__float2half_rn(v.x));
        p.y = __half_as_ushort(__float2half_rn(v.y));
        p.z = __half_as_ushort(__float2half_rn(v.z));
        p.w = __half_as_ushort(__float2half_rn(v.w));
        if (isx) ((ushort4*)g_xh)[i] = p;
        else     ((ushort4*)g_wh)[i] = p;
    } else {
        __shared__ int flg[2];
        const unsigned char* bb = (const unsigned char*)mraw;
        if (t < 2) flg[t] = 0;
        __syncthreads();
        int f_wide = 0, f_byte = 0;
        for (int i = t; i < Mq; i += 256) {
            unsigned char v = bb[i];
            if (v > 1) f_wide = 1;
            if (v && (i & 3)) f_byte = 1;
        }
        if (f_wide) atomicOr(&flg[0], 1);
        if (f_byte) atomicOr(&flg[1], 1);
        __syncthreads();
        const int wide = flg[0], byt = flg[1];
        for (int i = t; i < Mq; i += 256) {
            float m;
            if (wide)      m = (((const float*)mraw)[i] != 0.f) ? 1.f : 0.f;
            else if (byt)  m = bb[i] ? 1.f : 0.f;
            else           m = (((const int*)mraw)[i] != 0) ? 1.f : 0.f;
            g_mask[i] = m;
        }
    }
}

// ================= GEMM1 (single-pass fp16 HMMA) + bias + exact GELU =================
// tile 128(M) x 96(N), BK=64, 256 thr, 8 warps as 2(Mgrp) x 4(Ngrp), warp tile 64x24
__global__ __launch_bounds__(256, 2) void gemm_mma_kernel(const float* __restrict__ bias)
{
    extern __shared__ char smem[];
    const uint32_t sbase = smem_u32(smem);
    const int tid  = threadIdx.x;
    const int wid  = tid >> 5, lane = tid & 31;
    const int m0 = blockIdx.y * 128;
    const int n0 = blockIdx.x * 96;
    const int wr = wid & 1;          // 2 row groups of 64
    const int wc = wid >> 1;         // 4 col groups of 24

    float acc[4][3][4];
#pragma unroll
    for (int i = 0; i < 4; i++)
#pragma unroll
        for (int j = 0; j < 3; j++)
#pragma unroll
            for (int q = 0; q < 4; q++) acc[i][j][q] = 0.f;

    // loader: each thread copies ch-th 16B chunk of rows rr, rr+32, ...
    const int ch = tid & 7;          // 0..7 (16B chunk within 128B row)
    const int rr = tid >> 3;         // 0..31
    const __half* paw = g_xh + (size_t)(m0 + rr) * Dq + ch * 8;
    const __half* pbw = g_wh + (size_t)(n0 + rr) * Dq + ch * 8;

#define ISSUE(c, s)                                                       \
    do {                                                                  \
        const uint32_t d = sbase + (uint32_t)(s) * STG;                   \
        const int k0 = (c) * 64;                                          \
        const uint32_t da = d + AOF + (uint32_t)rr * ROWB + (uint32_t)ch * 16; \
        _Pragma("unroll")                                                 \
        for (int i = 0; i < 4; ++i)                                       \
            cp16(da + i * (32u * ROWB), paw + k0 + (size_t)(32 * i) * Dq);\
        const uint32_t db = d + BOF + (uint32_t)rr * ROWB + (uint32_t)ch * 16; \
        _Pragma("unroll")                                                 \
        for (int i = 0; i < 3; ++i)                                       \
            cp16(db + i * (32u * ROWB), pbw + k0 + (size_t)(32 * i) * Dq);\
        cp_commit();                                                      \
    } while (0)

    // ldmatrix lane address components
    const uint32_t a_ad  = AOF + (uint32_t)(wr * 64 + (lane & 15)) * ROWB + ((uint32_t)(lane >> 4) << 4);
    const uint32_t b4_ad = BOF + (uint32_t)(wc * 24 + ((lane >> 4) << 3) + (lane & 7)) * ROWB
                               + (((uint32_t)(lane >> 3) & 1u) << 4);
    const uint32_t b2_ad = BOF + (uint32_t)(wc * 24 + 16 + (lane & 7)) * ROWB
                               + (((uint32_t)(lane >> 3) & 1u) << 4);

    ISSUE(0, 0);
    ISSUE(1, 1);
    for (int c = 0; c < NC; ++c) {
        const int s = c % NSTG;
        if (c + 2 < NC) ISSUE(c + 2, (c + 2) % NSTG);
        if (c + 2 < NC)       cp_wait<2>();
        else if (c + 1 < NC)  cp_wait<1>();
        else                  cp_wait<0>();
        __syncthreads();

        const uint32_t base = sbase + (uint32_t)s * STG;
#pragma unroll
        for (int k16 = 0; k16 < 4; ++k16) {
            const uint32_t ko = (uint32_t)k16 * 32;
            uint32_t a[4][4], b4[4], b2r[2];
#pragma unroll
            for (int i = 0; i < 4; ++i)
                ldmx4(a[i], base + a_ad + (uint32_t)(i * 16) * ROWB + ko);
            ldmx4(b4, base + b4_ad + ko);
            ldmx2(b2r, base + b2_ad + ko);
#pragma unroll
            for (int i = 0; i < 4; ++i) {
                mma16816(acc[i][0], a[i], &b4[0]);
                mma16816(acc[i][1], a[i], &b4[2]);
                mma16816(acc[i][2], a[i], b2r);
            }
        }
        __syncthreads();
    }

    // Epilogue: + bias, exact GELU, store h (fp32)
#pragma unroll
    for (int i = 0; i < 4; ++i) {
        const int row0 = m0 + wr * 64 + i * 16 + (lane >> 2);
#pragma unroll
        for (int j = 0; j < 3; ++j) {
            const int col = n0 + wc * 24 + j * 8 + (lane & 3) * 2;
            const float b0 = bias[col], b1 = bias[col + 1];
            float v0 = acc[i][j][0] + b0, v1 = acc[i][j][1] + b1;
            float v2 = acc[i][j][2] + b0, v3 = acc[i][j][3] + b1;
            float2 o01, o23;
            o01.x = v0 * normcdff(v0); o01.y = v1 * normcdff(v1);
            o23.x = v2 * normcdff(v2); o23.y = v3 * normcdff(v3);
            *(float2*)(g_h + (size_t)row0 * Dq + col)       = o01;
            *(float2*)(g_h + (size_t)(row0 + 8) * Dq + col) = o23;
        }
    }
}

// ================= LN + 9-way head GEMM + geometry epilogue =================
__global__ __launch_bounds__(128) void head_kernel(
    const float* __restrict__ ln_g, const float* __restrict__ ln_b,
    const float* __restrict__ w2,   const float* __restrict__ b2,
    const float* __restrict__ affine, float* __restrict__ out)
{
    const int row = blockIdx.x;
    const int t = threadIdx.x;
    const int warp = t >> 5, lane = t & 31;
    __shared__ float rstat[2][4];
    __shared__ float red[9][4];

    const float* hrow = g_h + (size_t)row * Dq;
    float v[12];
    float s = 0.f, s2 = 0.f;
#pragma unroll
    for (int i = 0; i < 12; i++) {
        float x = hrow[t + i * 128];
        v[i] = x; s += x; s2 += x * x;
    }
#pragma unroll
    for (int off = 16; off > 0; off >>= 1) {
        s  += __shfl_down_sync(0xffffffffu, s,  off);
        s2 += __shfl_down_sync(0xffffffffu, s2, off);
    }
    if (lane == 0) { rstat[0][warp] = s; rstat[1][warp] = s2; }
    __syncthreads();
    const float S  = rstat[0][0] + rstat[0][1] + rstat[0][2] + rstat[0][3];
    const float Q  = rstat[1][0] + rstat[1][1] + rstat[1][2] + rstat[1][3];
    const float mu = S * (1.f / Dq);
    const float var = Q * (1.f / Dq) - mu * mu;
    const float rs = rsqrtf(var + 1e-5f);

    float acc[9];
#pragma unroll
    for (int o = 0; o < 9; o++) acc[o] = 0.f;
#pragma unroll
    for (int i = 0; i < 12; i++) {
        const int d = t + i * 128;
        const float hv = (v[i] - mu) * rs * ln_g[d] + ln_b[d];
#pragma unroll
        for (int o = 0; o < 9; o++) acc[o] += hv * w2[o * Dq + d];
    }
#pragma unroll
    for (int o = 0; o < 9; o++)
#pragma unroll
        for (int off = 16; off > 0; off >>= 1)
            acc[o] += __shfl_down_sync(0xffffffffu, acc[o], off);
    if (lane == 0) {
#pragma unroll
        for (int o = 0; o < 9; o++) red[o][warp] = acc[o];
    }
    __syncthreads();

    if (t == 0) {
        float p[9];
#pragma unroll
        for (int o = 0; o < 9; o++)
            p[o] = red[o][0] + red[o][1] + red[o][2] + red[o][3] + b2[o];

        float tr0 = p[0] * 10.f, tr1 = p[1] * 10.f, tr2 = p[2] * 10.f;
        float xv0 = p[3], xv1 = p[4], xv2 = p[5];
        float yv0 = p[6], yv1 = p[7], yv2 = p[8];
        float inx = 1.f / (sqrtf(xv0 * xv0 + xv1 * xv1 + xv2 * xv2) + 1e-5f);
        xv0 *= inx; xv1 *= inx; xv2 *= inx;
        float iny = 1.f / (sqrtf(yv0 * yv0 + yv1 * yv1 + yv2 * yv2) + 1e-5f);
        yv0 *= iny; yv1 *= iny; yv2 *= iny;

        float a0 = -xv0, a1 = -xv1, a2 = -xv2;
        float an = rsqrtf(a0 * a0 + a1 * a1 + a2 * a2 + 1e-12f);
        float e0x = a0 * an, e0y = a1 * an, e0z = a2 * an;
        float dd = e0x * yv0 + e0y * yv1 + e0z * yv2;
        float e1x = yv0 - e0x * dd, e1y = yv1 - e0y * dd, e1z = yv2 - e0z * dd;
        float en = rsqrtf(e1x * e1x + e1y * e1y + e1z * e1z + 1e-12f);
        e1x *= en; e1y *= en; e1z *= en;
        float e2x = e0y * e1z - e0z * e1y;
        float e2y = e0z * e1x - e0x * e1z;
        float e2z = e0x * e1y - e0y * e1x;

        float Ru[3][3] = {{e0x, e1x, e2x}, {e0y, e1y, e2y}, {e0z, e1z, e2z}};
        float tu0 = tr0, tu1 = tr1, tu2 = tr2;
        if (g_mask[row] == 0.f) {
            Ru[0][0] = 1.f; Ru[0][1] = 0.f; Ru[0][2] = 0.f;
            Ru[1][0] = 0.f; Ru[1][1] = 1.f; Ru[1][2] = 0.f;
            Ru[2][0] = 0.f; Ru[2][1] = 0.f; Ru[2][2] = 1.f;
            tu0 = 0.f; tu1 = 0.f; tu2 = 0.f;
        }

        const float* af = affine + (size_t)row * 12;
        float R0m[3][3] = {{af[0], af[1], af[2]}, {af[3], af[4], af[5]}, {af[6], af[7], af[8]}};
        float t0x = af[9], t0y = af[10], t0z = af[11];

        float R[3][3], tt[3];
#pragma unroll
        for (int i = 0; i < 3; i++) {
#pragma unroll
            for (int j = 0; j < 3; j++)
                R[i][j] = R0m[i][0] * Ru[0][j] + R0m[i][1] * Ru[1][j] + R0m[i][2] * Ru[2][j];
        }
        tt[0] = R0m[0][0] * tu0 + R0m[0][1] * tu1 + R0m[0][2] * tu2 + t0x;
        tt[1] = R0m[1][0] * tu0 + R0m[1][1] * tu1 + R0m[1][2] * tu2 + t0y;
        tt[2] = R0m[2][0] * tu0 + R0m[2][1] * tu1 + R0m[2][2] * tu2 + t0z;

        float* oa = out + (size_t)row * 12;
        oa[0] = R[0][0]; oa[1] = R[0][1]; oa[2] = R[0][2];
        oa[3] = R[1][0]; oa[4] = R[1][1]; oa[5] = R[1][2];
        oa[6] = R[2][0]; oa[7] = R[2][1]; oa[8] = R[2][2];
        oa[9] = tt[0]; oa[10] = tt[1]; oa[11] = tt[2];

        const float BBc[3][3] = {{-0.525f, 1.363f, 0.f}, {0.f, 0.f, 0.f}, {1.526f, 0.f, 0.f}};
        float* ox = out + (size_t)Mq * 12 + (size_t)row * 9;
#pragma unroll
        for (int a = 0; a < 3; a++) {
#pragma unroll
            for (int i = 0; i < 3; i++)
                ox[a * 3 + i] = R[i][0] * BBc[a][0] + R[i][1] * BBc[a][1] + R[i][2] * BBc[a][2] + tt[i];
        }
    }
}

// ================= launcher =================
extern "C" void kernel_launch(void* const* d_in, const int* in_sizes, int n_in,
                              void* d_out, int out_size) {
    const float* x      = (const float*)d_in[0];
    const float* affine = (const float*)d_in[1];
    const void*  mraw   = d_in[2];
    const float* w1     = (const float*)d_in[3];
    const float* b1     = (const float*)d_in[4];
    const float* ln_g   = (const float*)d_in[5];
    const float* ln_b   = (const float*)d_in[6];
    const float* w2     = (const float*)d_in[7];
    const float* b2     = (const float*)d_in[8];
    float* out = (float*)d_out;
    (void)in_sizes; (void)n_in; (void)out_size;

    static int attr_set = 0;
    if (!attr_set) {
        cudaFuncSetAttribute(gemm_mma_kernel, cudaFuncAttributeMaxDynamicSharedMemorySize, SMEM_TOTAL);
        attr_set = 1;
    }

    prep_kernel<<<XBLK2 + WBLK2 + 1, 256>>>(x, w1, mraw);
    dim3 grid(Dq / 96, Mq / 128);   // (16, 32)
    gemm_mma_kernel<<<grid, 256, SMEM_TOTAL>>>(b1);
    head_kernel<<<Mq, 128>>>(ln_g, ln_b, w2, b2, affine, out);
}